// round 7
// baseline (speedup 1.0000x reference)
#include <cuda_runtime.h>
#include <mma.h>
#include <cstdint>

using namespace nvcuda;

#define CCH 32
#define HH 224
#define WW 224
#define BB 16
#define KELEMS (CCH*9)   // 288 weight elems per out channel

// ---------------- device scratch ----------------
// conv1 weights int8: [pos 9][co 32][128 = plane*32+ci], weight replicated per plane
__device__ signed char g_w1b[9*CCH*128];
// conv2 weights packed int8x4 over ci groups: [cig][k][co]
__device__ int   g_w2[(CCH/4)*9*CCH];
// LUT params
__device__ float g_lut1_t0[CCH], g_lut1_d[CCH];
__device__ int   g_lut2_t0[CCH], g_lut2_d[CCH];
// quantized input: per pixel 128 bytes [plane*32+ci], q = rint(x*2^24) signed-digit
__device__ unsigned int g_xt[(size_t)BB*HH*WW*32];   // 32 words = 128 B per pixel
// intermediate levels, 4 channels packed per uint32: [n][cig][h][w]
__device__ unsigned int g_mid[(size_t)BB*(CCH/4)*HH*WW];

// ---------------------------------------------------------------------------
// Setup: binarize weights and fold BN into integer LUTs
// ---------------------------------------------------------------------------
__global__ void setup_kernel(const float* __restrict__ conv1_w,
                             const float* __restrict__ conv2_w,
                             const float* __restrict__ bn1_w, const float* __restrict__ bn1_b,
                             const float* __restrict__ bn1_m, const float* __restrict__ bn1_v,
                             const float* __restrict__ bn2_w, const float* __restrict__ bn2_b,
                             const float* __restrict__ bn2_m, const float* __restrict__ bn2_v,
                             const float* __restrict__ a1p, const float* __restrict__ a2p,
                             const float* __restrict__ nsp) {
    __shared__ float red[KELEMS];
    __shared__ float mean1s, mean2s;
    __shared__ int   ssm[KELEMS];
    int co = blockIdx.x;
    int t  = threadIdx.x;           // 288 threads

    float v1 = conv1_w[co*KELEMS + t];
    float v2 = conv2_w[co*KELEMS + t];

    red[t] = v1; __syncthreads();
    if (t < 32) red[t] += red[t + 256];
    __syncthreads();
    for (int s = 128; s > 0; s >>= 1) { if (t < s) red[t] += red[t + s]; __syncthreads(); }
    if (t == 0) mean1s = red[0] * (1.f / 288.f);
    __syncthreads();
    float m1 = mean1s;
    __syncthreads();

    red[t] = v2; __syncthreads();
    if (t < 32) red[t] += red[t + 256];
    __syncthreads();
    for (int s = 128; s > 0; s >>= 1) { if (t < s) red[t] += red[t + s]; __syncthreads(); }
    if (t == 0) mean2s = red[0] * (1.f / 288.f);
    __syncthreads();
    float m2 = mean2s;

    int ci = t / 9, k = t % 9;
    {   // conv1 weight int8, replicated for each of the 4 planes
        float d1 = v1 - m1;
        signed char s8 = (d1 > 0.f) ? 1 : ((d1 < 0.f) ? -1 : 0);
        int rowb = (k*CCH + co)*128;
        g_w1b[rowb +  0 + ci] = s8;
        g_w1b[rowb + 32 + ci] = s8;
        g_w1b[rowb + 64 + ci] = s8;
        g_w1b[rowb + 96 + ci] = s8;
    }

    float s2f = v2 - m2;
    ssm[t] = (s2f > 0.f) ? 1 : ((s2f < 0.f) ? -1 : 0);
    __syncthreads();
    if (t < (CCH/4)*9) {
        int cig = t / 9, kk = t % 9;
        int pk = 0;
        #pragma unroll
        for (int b = 0; b < 4; b++) {
            int s = ssm[(cig*4 + b)*9 + kk];
            pk |= (s & 0xFF) << (8*b);
        }
        g_w2[(cig*9 + kk)*CCH + co] = pk;
    }

    if (t == 0) {
        float a1 = *a1p, a2 = *a2p, ns = *nsp;
        {
            float std = sqrtf(bn1_v[co] + 1e-5f);
            float w = bn1_w[co] / std;
            float b = bn1_b[co] - w * bn1_m[co];
            float den = a1 * w;
            float t0 = rintf((0.5f * a2 - b) / den);
            float t1 = rintf((1.5f * a2 - b) / den);
            g_lut1_t0[co] = t0;
            g_lut1_d[co]  = t1 - t0;
        }
        {
            float std = sqrtf(bn2_v[co] + 1e-5f);
            float w = bn2_w[co] / std;
            float b = bn2_b[co] - w * bn2_m[co];
            float den = a2 * w;
            float t0 = rintf((0.5f * ns - b) / den);
            float t1 = rintf((1.5f * ns - b) / den);
            g_lut2_t0[co] = (int)t0;
            g_lut2_d[co]  = (int)(t1 - t0);
        }
    }
}

// ---------------------------------------------------------------------------
// Pre-pass: NCHW fp32 -> per-pixel 128 int8 [plane*32+ci], q = rint(x*2^24)
// signed-digit base-256 decomposition (exact: q = b0 + 256 b1 + 2^16 b2 + 2^24 b3)
// ---------------------------------------------------------------------------
__global__ void __launch_bounds__(256)
prepass_kernel(const float* __restrict__ x) {
    __shared__ signed char stage[WW*132];   // [w][132]: 4B pad per pixel slot
    int n = blockIdx.y, h = blockIdx.x;
    int tid = threadIdx.x;

    for (int idx = tid; idx < CCH*WW; idx += 256) {
        int ci = idx / WW, w = idx % WW;        // lanes: w consecutive -> coalesced
        float v = x[(((size_t)n*CCH + ci)*HH + h)*WW + w];
        int q = __float2int_rn(v * 16777216.f);
        int b0 = (int)(signed char)(q & 0xFF);
        int q1 = (q - b0) >> 8;
        int b1 = (int)(signed char)(q1 & 0xFF);
        int q2 = (q1 - b1) >> 8;
        int b2 = (int)(signed char)(q2 & 0xFF);
        int b3 = (q2 - b2) >> 8;                 // |b3| <= 8
        stage[w*132 +  0 + ci] = (signed char)b0;
        stage[w*132 + 32 + ci] = (signed char)b1;
        stage[w*132 + 64 + ci] = (signed char)b2;
        stage[w*132 + 96 + ci] = (signed char)b3;
    }
    __syncthreads();
    const unsigned* sw = (const unsigned*)stage;
    unsigned* dst = g_xt + ((size_t)n*HH + h)*WW*32;
    for (int idx = tid; idx < WW*32; idx += 256) {
        int w = idx >> 5, c = idx & 31;
        dst[idx] = sw[w*33 + c];                // coalesced dst
    }
}

// ---------------------------------------------------------------------------
// Conv1 via int8 WMMA (IMMA, exact), fused LUT1 (exact int64 compare) -> g_mid
// CTA: 256 threads / 8 warps. Output tile: 8h x 16w x 32co. Warp owns row oh=wid.
// K per plane = 9 pos x 32 ci; 4 planes in 4 separate int32 accumulators.
// Patch P[10][18] slots x 144B (conflict-free ldsm); Weights Wt[9*32] x 144B.
// ---------------------------------------------------------------------------
#define PSTR8 144
#define P_BYTES (180*PSTR8)           // 25920
#define W_BYTES (288*PSTR8)           // 41472
#define E_LD   36
#define SMEM1_TOT (P_BYTES + W_BYTES) // 67392

__global__ void __launch_bounds__(256)
conv1_imma_kernel() {
    extern __shared__ __align__(16) char smem[];
    signed char* P  = (signed char*)smem;            // [180][144]
    signed char* Wt = (signed char*)(smem + P_BYTES);// [288][144]
    unsigned* P32 = (unsigned*)P;
    unsigned* W32 = (unsigned*)Wt;

    int tid = threadIdx.x;
    int wid = tid >> 5, lid = tid & 31;

    int n  = blockIdx.z;
    int h0 = blockIdx.y * 8;
    int w0 = blockIdx.x * 16;

    // weights: 288 rows x 32 words (row stride 36 words)
    for (int r = wid; r < 9*32; r += 8) {
        W32[r*36 + lid] = ((const unsigned*)g_w1b)[r*32 + lid];
    }
    // patch: 10x18 pixel slots x 32 words
    for (int r = wid; r < 10*18; r += 8) {
        int ph = r / 18, pw = r % 18;
        int gh = h0 - 1 + ph, gw = w0 - 1 + pw;
        bool ok = (gh >= 0 && gh < HH && gw >= 0 && gw < WW);
        const unsigned* src = g_xt + (((size_t)n*HH + (ok ? gh : 0))*WW + (ok ? gw : 0))*32;
        P32[r*36 + lid] = ok ? src[lid] : 0u;
    }
    __syncthreads();

    wmma::fragment<wmma::accumulator, 16, 16, 16, int> c[4][2];
    #pragma unroll
    for (int p = 0; p < 4; p++) {
        wmma::fill_fragment(c[p][0], 0);
        wmma::fill_fragment(c[p][1], 0);
    }

    int oh = wid;
    #pragma unroll
    for (int kh = 0; kh < 3; kh++) {
        #pragma unroll
        for (int kw = 0; kw < 3; kw++) {
            const signed char* abase = P + ((oh + kh)*18 + kw)*PSTR8;
            const signed char* bbase = Wt + (kh*3 + kw)*32*PSTR8;
            #pragma unroll
            for (int p = 0; p < 4; p++) {
                #pragma unroll
                for (int ch = 0; ch < 2; ch++) {
                    int koff = p*32 + ch*16;
                    wmma::fragment<wmma::matrix_a, 16, 16, 16, signed char, wmma::row_major> a;
                    wmma::load_matrix_sync(a, abase + koff, PSTR8);
                    wmma::fragment<wmma::matrix_b, 16, 16, 16, signed char, wmma::col_major> b0, b1;
                    wmma::load_matrix_sync(b0, bbase + koff, PSTR8);
                    wmma::load_matrix_sync(b1, bbase + 16*PSTR8 + koff, PSTR8);
                    wmma::mma_sync(c[p][0], a, b0, c[p][0]);
                    wmma::mma_sync(c[p][1], a, b1, c[p][1]);
                }
            }
        }
    }

    // combine planes pairwise (exact, fits int32): P01 = P0 + (P1<<8), P23 = P2 + (P3<<8)
    #pragma unroll
    for (int nf = 0; nf < 2; nf++) {
        #pragma unroll
        for (int i = 0; i < c[0][nf].num_elements; i++) {
            c[0][nf].x[i] += (c[1][nf].x[i] << 8);
            c[2][nf].x[i] += (c[3][nf].x[i] << 8);
        }
    }

    __syncthreads();                     // all P/Wt reads done; overlay epilogue
    int* E = (int*)smem;                 // [8 warps][16][E_LD]
    int* e = E + wid*16*E_LD;

    wmma::store_matrix_sync(e,      c[0][0], E_LD, wmma::mem_row_major);
    wmma::store_matrix_sync(e + 16, c[0][1], E_LD, wmma::mem_row_major);
    __syncwarp();
    int pw = lid & 15, chalf = lid >> 4;
    int v01[16];
    #pragma unroll
    for (int t = 0; t < 16; t++) v01[t] = e[pw*E_LD + chalf*16 + t];
    __syncwarp();
    wmma::store_matrix_sync(e,      c[2][0], E_LD, wmma::mem_row_major);
    wmma::store_matrix_sync(e + 16, c[2][1], E_LD, wmma::mem_row_major);
    __syncwarp();

    int gh = h0 + oh, gw = w0 + pw;
    #pragma unroll
    for (int jw = 0; jw < 4; jw++) {
        unsigned word = 0;
        #pragma unroll
        for (int b = 0; b < 4; b++) {
            int t = jw*4 + b;
            int co = chalf*16 + t;
            long long S = (long long)v01[t]
                        + ((long long)e[pw*E_LD + chalf*16 + t] << 16);
            long long T0 = (long long)g_lut1_t0[co];
            long long D  = (long long)g_lut1_d[co];
            int lvl = 0;
            #pragma unroll
            for (int jj = 0; jj < 7; jj++) {
                long long th = (T0 + (long long)jj * D) << 24;
                lvl += (jj & 1) ? (S >= th) : (S > th);
            }
            word |= (unsigned)lvl << (8*b);
        }
        int cig = chalf*4 + jw;
        g_mid[(((size_t)n*(CCH/4) + cig)*HH + gh)*WW + gw] = word;
    }
}

// ---------------------------------------------------------------------------
// Conv2 (exact int8 via dp4a, weights ±1) fused with LUT2 -> fp32 output
// ---------------------------------------------------------------------------
__device__ __forceinline__ unsigned load_mid(const unsigned* __restrict__ mn, int cig,
                                             int idx, int h0, int w0) {
    int ph = idx / 18, pw = idx % 18;
    int gh = h0 - 1 + ph, gw = w0 - 1 + pw;
    if (gh < 0 || gh >= HH || gw < 0 || gw >= WW) return 0u;
    return mn[(size_t)cig*HH*WW + gh*WW + gw];
}

__global__ void __launch_bounds__(256, 2)
conv2_kernel(float* __restrict__ out) {
    __shared__ int ws2[(CCH/4)*9*CCH];     // 9216 B
    __shared__ unsigned patch[2][18*18];

    int n  = blockIdx.z;
    int h0 = blockIdx.y * 16, w0 = blockIdx.x * 16;
    int tid = threadIdx.x;

    for (int i = tid; i < (CCH/4)*9*CCH; i += 256) ws2[i] = g_w2[i];

    int cog = tid >> 6;
    int p0  = tid & 63;

    int acc[4][8];
    #pragma unroll
    for (int p = 0; p < 4; p++)
        #pragma unroll
        for (int j = 0; j < 8; j++) acc[p][j] = 0;

    const unsigned* mn = g_mid + (size_t)n*(CCH/4)*HH*WW;

    unsigned r0 = load_mid(mn, 0, tid, h0, w0);
    unsigned r1 = (tid + 256 < 324) ? load_mid(mn, 0, tid + 256, h0, w0) : 0u;

    for (int cig = 0; cig < CCH/4; cig++) {
        int buf = cig & 1;
        patch[buf][tid] = r0;
        if (tid + 256 < 324) patch[buf][tid + 256] = r1;
        __syncthreads();
        if (cig + 1 < CCH/4) {
            r0 = load_mid(mn, cig + 1, tid, h0, w0);
            r1 = (tid + 256 < 324) ? load_mid(mn, cig + 1, tid + 256, h0, w0) : 0u;
        }
        const int* wp = &ws2[cig*9*CCH + cog*8];
        #pragma unroll
        for (int k = 0; k < 9; k++) {
            int kh = k / 3, kw = k % 3;
            int4 wa = *(const int4*)(wp + k*CCH);
            int4 wb = *(const int4*)(wp + k*CCH + 4);
            #pragma unroll
            for (int p = 0; p < 4; p++) {
                int pix = p0 + 64*p;
                int hh = pix >> 4, wc = pix & 15;
                int xv = (int)patch[buf][(hh + kh)*18 + wc + kw];
                acc[p][0] = __dp4a(xv, wa.x, acc[p][0]);
                acc[p][1] = __dp4a(xv, wa.y, acc[p][1]);
                acc[p][2] = __dp4a(xv, wa.z, acc[p][2]);
                acc[p][3] = __dp4a(xv, wa.w, acc[p][3]);
                acc[p][4] = __dp4a(xv, wb.x, acc[p][4]);
                acc[p][5] = __dp4a(xv, wb.y, acc[p][5]);
                acc[p][6] = __dp4a(xv, wb.z, acc[p][6]);
                acc[p][7] = __dp4a(xv, wb.w, acc[p][7]);
            }
        }
        __syncthreads();
    }

    int IT0[8], ID[8];
    #pragma unroll
    for (int j = 0; j < 8; j++) {
        IT0[j] = g_lut2_t0[cog*8 + j];
        ID[j]  = g_lut2_d[cog*8 + j];
    }
    #pragma unroll
    for (int p = 0; p < 4; p++) {
        int pix = p0 + 64*p;
        int hh = pix >> 4, wc = pix & 15;
        int gh = h0 + hh, gw = w0 + wc;
        #pragma unroll
        for (int j = 0; j < 8; j++) {
            int s = acc[p][j];
            int lvl = 0;
            #pragma unroll
            for (int jj = 0; jj < 7; jj++) {
                int th = IT0[j] + jj * ID[j];
                lvl += (jj & 1) ? (s >= th) : (s > th);
            }
            int co = cog*8 + j;
            out[(((size_t)n*CCH + co)*HH + gh)*WW + gw] = (float)lvl;
        }
    }
}

// ---------------------------------------------------------------------------
extern "C" void kernel_launch(void* const* d_in, const int* in_sizes, int n_in,
                              void* d_out, int out_size) {
    const float* x       = (const float*)d_in[0];
    const float* conv1_w = (const float*)d_in[1];
    const float* conv2_w = (const float*)d_in[2];
    const float* bn1_w   = (const float*)d_in[3];
    const float* bn1_b   = (const float*)d_in[4];
    const float* bn1_m   = (const float*)d_in[5];
    const float* bn1_v   = (const float*)d_in[6];
    const float* bn2_w   = (const float*)d_in[7];
    const float* bn2_b   = (const float*)d_in[8];
    const float* bn2_m   = (const float*)d_in[9];
    const float* bn2_v   = (const float*)d_in[10];
    const float* a1      = (const float*)d_in[11];
    const float* a2      = (const float*)d_in[12];
    const float* ns      = (const float*)d_in[13];

    setup_kernel<<<CCH, KELEMS>>>(conv1_w, conv2_w,
                                  bn1_w, bn1_b, bn1_m, bn1_v,
                                  bn2_w, bn2_b, bn2_m, bn2_v,
                                  a1, a2, ns);

    dim3 pgrid(HH, BB);
    prepass_kernel<<<pgrid, 256>>>(x);

    cudaFuncSetAttribute(conv1_imma_kernel,
                         cudaFuncAttributeMaxDynamicSharedMemorySize, SMEM1_TOT);
    dim3 grid1(WW/16, HH/8, BB);
    conv1_imma_kernel<<<grid1, 256, SMEM1_TOT>>>();

    dim3 grid2(WW/16, HH/16, BB);
    conv2_kernel<<<grid2, 256>>>((float*)d_out);
}

// round 8
// speedup vs baseline: 1.6060x; 1.6060x over previous
#include <cuda_runtime.h>
#include <cstdint>

#define CCH 32
#define HH 224
#define WW 224
#define BB 16
#define KELEMS (CCH*9)   // 288 weight elems per out channel

// ---------------- device scratch ----------------
// conv1 weights int8: [pos 9][co 32][128 = plane*32+ci], weight replicated per plane
__device__ signed char g_w1b[9*CCH*128];
// conv2 weights packed int8x4 over ci groups: [cig][k][co]
__device__ int   g_w2[(CCH/4)*9*CCH];
// LUT params
__device__ float g_lut1_t0[CCH], g_lut1_d[CCH];
__device__ int   g_lut2_t0[CCH], g_lut2_d[CCH];
// quantized input: per pixel 128 bytes [plane*32+ci], q = rint(x*2^24) signed-digit
__device__ unsigned int g_xt[(size_t)BB*HH*WW*32];   // 32 words = 128 B per pixel
// intermediate levels, 4 channels packed per uint32: [n][cig][h][w]
__device__ unsigned int g_mid[(size_t)BB*(CCH/4)*HH*WW];

// ---------------- PTX helpers ----------------
#define LDSM4(r0,r1,r2,r3,addr)                                              \
    asm volatile("ldmatrix.sync.aligned.m8n8.x4.shared.b16 {%0,%1,%2,%3}, [%4];" \
        : "=r"(r0), "=r"(r1), "=r"(r2), "=r"(r3) : "r"(addr))

#define MMA_S8(c0,c1,c2,c3,a0,a1,a2,a3,b0,b1)                                \
    asm("mma.sync.aligned.m16n8k32.row.col.s32.s8.s8.s32 "                   \
        "{%0,%1,%2,%3}, {%4,%5,%6,%7}, {%8,%9}, {%0,%1,%2,%3};"              \
        : "+r"(c0), "+r"(c1), "+r"(c2), "+r"(c3)                             \
        : "r"(a0), "r"(a1), "r"(a2), "r"(a3), "r"(b0), "r"(b1))

// ---------------------------------------------------------------------------
// Setup: binarize weights and fold BN into integer LUTs
// ---------------------------------------------------------------------------
__global__ void setup_kernel(const float* __restrict__ conv1_w,
                             const float* __restrict__ conv2_w,
                             const float* __restrict__ bn1_w, const float* __restrict__ bn1_b,
                             const float* __restrict__ bn1_m, const float* __restrict__ bn1_v,
                             const float* __restrict__ bn2_w, const float* __restrict__ bn2_b,
                             const float* __restrict__ bn2_m, const float* __restrict__ bn2_v,
                             const float* __restrict__ a1p, const float* __restrict__ a2p,
                             const float* __restrict__ nsp) {
    __shared__ float red[KELEMS];
    __shared__ float mean1s, mean2s;
    __shared__ int   ssm[KELEMS];
    int co = blockIdx.x;
    int t  = threadIdx.x;           // 288 threads

    float v1 = conv1_w[co*KELEMS + t];
    float v2 = conv2_w[co*KELEMS + t];

    red[t] = v1; __syncthreads();
    if (t < 32) red[t] += red[t + 256];
    __syncthreads();
    for (int s = 128; s > 0; s >>= 1) { if (t < s) red[t] += red[t + s]; __syncthreads(); }
    if (t == 0) mean1s = red[0] * (1.f / 288.f);
    __syncthreads();
    float m1 = mean1s;
    __syncthreads();

    red[t] = v2; __syncthreads();
    if (t < 32) red[t] += red[t + 256];
    __syncthreads();
    for (int s = 128; s > 0; s >>= 1) { if (t < s) red[t] += red[t + s]; __syncthreads(); }
    if (t == 0) mean2s = red[0] * (1.f / 288.f);
    __syncthreads();
    float m2 = mean2s;

    int ci = t / 9, k = t % 9;
    {   // conv1 weight int8, replicated for each of the 4 planes
        float d1 = v1 - m1;
        signed char s8 = (d1 > 0.f) ? 1 : ((d1 < 0.f) ? -1 : 0);
        int rowb = (k*CCH + co)*128;
        g_w1b[rowb +  0 + ci] = s8;
        g_w1b[rowb + 32 + ci] = s8;
        g_w1b[rowb + 64 + ci] = s8;
        g_w1b[rowb + 96 + ci] = s8;
    }

    float s2f = v2 - m2;
    ssm[t] = (s2f > 0.f) ? 1 : ((s2f < 0.f) ? -1 : 0);
    __syncthreads();
    if (t < (CCH/4)*9) {
        int cig = t / 9, kk = t % 9;
        int pk = 0;
        #pragma unroll
        for (int b = 0; b < 4; b++) {
            int s = ssm[(cig*4 + b)*9 + kk];
            pk |= (s & 0xFF) << (8*b);
        }
        g_w2[(cig*9 + kk)*CCH + co] = pk;
    }

    if (t == 0) {
        float a1 = *a1p, a2 = *a2p, ns = *nsp;
        {
            float std = sqrtf(bn1_v[co] + 1e-5f);
            float w = bn1_w[co] / std;
            float b = bn1_b[co] - w * bn1_m[co];
            float den = a1 * w;
            float t0 = rintf((0.5f * a2 - b) / den);
            float t1 = rintf((1.5f * a2 - b) / den);
            g_lut1_t0[co] = t0;
            g_lut1_d[co]  = t1 - t0;
        }
        {
            float std = sqrtf(bn2_v[co] + 1e-5f);
            float w = bn2_w[co] / std;
            float b = bn2_b[co] - w * bn2_m[co];
            float den = a2 * w;
            float t0 = rintf((0.5f * ns - b) / den);
            float t1 = rintf((1.5f * ns - b) / den);
            g_lut2_t0[co] = (int)t0;
            g_lut2_d[co]  = (int)(t1 - t0);
        }
    }
}

// ---------------------------------------------------------------------------
// Pre-pass: NCHW fp32 -> per-pixel 128 int8 [plane*32+ci], q = rint(x*2^24)
// signed-digit base-256 decomposition (exact: q = b0 + 256 b1 + 2^16 b2 + 2^24 b3)
// ---------------------------------------------------------------------------
__global__ void __launch_bounds__(256)
prepass_kernel(const float* __restrict__ x) {
    __shared__ signed char stage[WW*132];   // [w][132]: 4B pad per pixel slot
    int n = blockIdx.y, h = blockIdx.x;
    int tid = threadIdx.x;

    for (int idx = tid; idx < CCH*WW; idx += 256) {
        int ci = idx / WW, w = idx % WW;        // lanes: w consecutive -> coalesced
        float v = x[(((size_t)n*CCH + ci)*HH + h)*WW + w];
        int q = __float2int_rn(v * 16777216.f);
        int b0 = (int)(signed char)(q & 0xFF);
        int q1 = (q - b0) >> 8;
        int b1 = (int)(signed char)(q1 & 0xFF);
        int q2 = (q1 - b1) >> 8;
        int b2 = (int)(signed char)(q2 & 0xFF);
        int b3 = (q2 - b2) >> 8;                 // |b3| <= 8
        stage[w*132 +  0 + ci] = (signed char)b0;
        stage[w*132 + 32 + ci] = (signed char)b1;
        stage[w*132 + 64 + ci] = (signed char)b2;
        stage[w*132 + 96 + ci] = (signed char)b3;
    }
    __syncthreads();
    const unsigned* sw = (const unsigned*)stage;
    unsigned* dst = g_xt + ((size_t)n*HH + h)*WW*32;
    for (int idx = tid; idx < WW*32; idx += 256) {
        int w = idx >> 5, c = idx & 31;
        dst[idx] = sw[w*33 + c];                // coalesced dst
    }
}

// ---------------------------------------------------------------------------
// Conv1 via raw IMMA m16n8k32 (exact), fused integer LUT1 -> g_mid
// CTA: 256 threads / 8 warps. Output tile: 8h x 16w x 32co. Warp owns row oh=wid.
// A: 16 w-pixels x 32 ci (one plane) per mma; B: 32co split in 4 n-tiles.
// Patch P[10][18] slots x 144B; Weights Wt[9*32] x 144B (16B-aligned rows).
// ---------------------------------------------------------------------------
#define PSTR8 144
#define P_BYTES (180*PSTR8)           // 25920
#define W_BYTES (288*PSTR8)           // 41472
#define SMEM1_TOT (P_BYTES + W_BYTES) // 67392

__global__ void __launch_bounds__(256)
conv1_imma_kernel() {
    extern __shared__ __align__(16) char smem[];
    signed char* P  = (signed char*)smem;            // [180][144]
    signed char* Wt = (signed char*)(smem + P_BYTES);// [288][144]
    unsigned* P32 = (unsigned*)P;
    unsigned* W32 = (unsigned*)Wt;

    int tid = threadIdx.x;
    int wid = tid >> 5, lid = tid & 31;

    int n  = blockIdx.z;
    int h0 = blockIdx.y * 8;
    int w0 = blockIdx.x * 16;

    // weights: 288 rows x 32 words (row stride 36 words)
    for (int r = wid; r < 9*32; r += 8) {
        W32[r*36 + lid] = ((const unsigned*)g_w1b)[r*32 + lid];
    }
    // patch: 10x18 pixel slots x 32 words
    for (int r = wid; r < 10*18; r += 8) {
        int ph = r / 18, pw = r % 18;
        int gh = h0 - 1 + ph, gw = w0 - 1 + pw;
        bool ok = (gh >= 0 && gh < HH && gw >= 0 && gw < WW);
        const unsigned* src = g_xt + (((size_t)n*HH + (ok ? gh : 0))*WW + (ok ? gw : 0))*32;
        P32[r*36 + lid] = ok ? src[lid] : 0u;
    }
    __syncthreads();

    unsigned Pb = (unsigned)__cvta_generic_to_shared(P);
    unsigned Wb = (unsigned)__cvta_generic_to_shared(Wt);

    // accumulators: [plane][ntile][reg]
    int c[4][4][4];
    #pragma unroll
    for (int p = 0; p < 4; p++)
        #pragma unroll
        for (int t = 0; t < 4; t++)
            #pragma unroll
            for (int i = 0; i < 4; i++) c[p][t][i] = 0;

    int oh = wid;
    // A ldmatrix lane mapping: tiles (px0-7,k0-15),(px8-15,k0-15),(px0-7,k16-31),(px8-15,k16-31)
    int apix  = (lid < 16) ? lid : (lid - 16);
    int akadd = (lid < 16) ? 0 : 16;
    // B ldmatrix lane mapping: tiles (co b..b+7,k lo),(same,k hi),(co b+8..b+15,k lo),(hi)
    int bco   = ((lid >> 4) << 3) + (lid & 7);
    int bkadd = ((lid >> 3) & 1) * 16;

    #pragma unroll 1
    for (int pos = 0; pos < 9; pos++) {
        int kh = pos / 3, kw = pos % 3;
        unsigned aaddr = Pb + (unsigned)(((oh + kh)*18 + kw + apix)*PSTR8 + akadd);
        unsigned baddr = Wb + (unsigned)((pos*32 + bco)*PSTR8 + bkadd);
        #pragma unroll
        for (int p = 0; p < 4; p++) {
            unsigned a0, a1, a2, a3;
            LDSM4(a0, a1, a2, a3, aaddr + p*32);
            unsigned b0, b1, b2, b3;
            LDSM4(b0, b1, b2, b3, baddr + p*32);                 // co 0-15
            unsigned b4, b5, b6, b7;
            LDSM4(b4, b5, b6, b7, baddr + 16*PSTR8 + p*32);      // co 16-31
            MMA_S8(c[p][0][0], c[p][0][1], c[p][0][2], c[p][0][3], a0, a1, a2, a3, b0, b1);
            MMA_S8(c[p][1][0], c[p][1][1], c[p][1][2], c[p][1][3], a0, a1, a2, a3, b2, b3);
            MMA_S8(c[p][2][0], c[p][2][1], c[p][2][2], c[p][2][3], a0, a1, a2, a3, b4, b5);
            MMA_S8(c[p][3][0], c[p][3][1], c[p][3][2], c[p][3][3], a0, a1, a2, a3, b6, b7);
        }
    }

    // epilogue: c regs -> exact int64 sums -> integer LUT -> pack via shfl
    // accum layout: reg0: (row=lid/4,   col=2*(lid%4)), reg1: col+1
    //               reg2: (row=lid/4+8, col=2*(lid%4)), reg3: col+1
    int gh  = h0 + oh;
    int row = lid >> 2;
    int colq = lid & 3;
    #pragma unroll
    for (int t = 0; t < 4; t++) {
        int co0 = 8*t + 2*colq;
        long long T0a = (long long)g_lut1_t0[co0],   Da = (long long)g_lut1_d[co0];
        long long T0b = (long long)g_lut1_t0[co0+1], Db = (long long)g_lut1_d[co0+1];
        unsigned half[2];
        #pragma unroll
        for (int rpair = 0; rpair < 2; rpair++) {   // 0: row, 1: row+8
            int i0 = rpair*2, i1 = rpair*2 + 1;
            long long S0 = (long long)(c[0][t][i0] + (c[1][t][i0] << 8))
                         + ((long long)(c[2][t][i0] + (c[3][t][i0] << 8)) << 16);
            long long S1 = (long long)(c[0][t][i1] + (c[1][t][i1] << 8))
                         + ((long long)(c[2][t][i1] + (c[3][t][i1] << 8)) << 16);
            int l0 = 0, l1 = 0;
            #pragma unroll
            for (int jj = 0; jj < 7; jj++) {
                long long tha = (T0a + (long long)jj * Da) << 24;
                long long thb = (T0b + (long long)jj * Db) << 24;
                l0 += (jj & 1) ? (S0 >= tha) : (S0 > tha);
                l1 += (jj & 1) ? (S1 >= thb) : (S1 > thb);
            }
            half[rpair] = (unsigned)l0 | ((unsigned)l1 << 8);
        }
        unsigned pA = __shfl_xor_sync(0xFFFFFFFFu, half[0], 1);
        unsigned pB = __shfl_xor_sync(0xFFFFFFFFu, half[1], 1);
        if (!(lid & 1)) {
            int cig = 2*t + (colq >> 1);
            size_t base = (((size_t)n*(CCH/4) + cig)*HH + gh)*WW + w0;
            g_mid[base + row]     = half[0] | (pA << 16);
            g_mid[base + row + 8] = half[1] | (pB << 16);
        }
    }
}

// ---------------------------------------------------------------------------
// Conv2 (exact int8 via dp4a, weights ±1) fused with LUT2 -> fp32 output
// ---------------------------------------------------------------------------
__device__ __forceinline__ unsigned load_mid(const unsigned* __restrict__ mn, int cig,
                                             int idx, int h0, int w0) {
    int ph = idx / 18, pw = idx % 18;
    int gh = h0 - 1 + ph, gw = w0 - 1 + pw;
    if (gh < 0 || gh >= HH || gw < 0 || gw >= WW) return 0u;
    return mn[(size_t)cig*HH*WW + gh*WW + gw];
}

__global__ void __launch_bounds__(256, 2)
conv2_kernel(float* __restrict__ out) {
    __shared__ int ws2[(CCH/4)*9*CCH];     // 9216 B
    __shared__ unsigned patch[2][18*18];

    int n  = blockIdx.z;
    int h0 = blockIdx.y * 16, w0 = blockIdx.x * 16;
    int tid = threadIdx.x;

    for (int i = tid; i < (CCH/4)*9*CCH; i += 256) ws2[i] = g_w2[i];

    int cog = tid >> 6;
    int p0  = tid & 63;

    int acc[4][8];
    #pragma unroll
    for (int p = 0; p < 4; p++)
        #pragma unroll
        for (int j = 0; j < 8; j++) acc[p][j] = 0;

    const unsigned* mn = g_mid + (size_t)n*(CCH/4)*HH*WW;

    unsigned r0 = load_mid(mn, 0, tid, h0, w0);
    unsigned r1 = (tid + 256 < 324) ? load_mid(mn, 0, tid + 256, h0, w0) : 0u;

    for (int cig = 0; cig < CCH/4; cig++) {
        int buf = cig & 1;
        patch[buf][tid] = r0;
        if (tid + 256 < 324) patch[buf][tid + 256] = r1;
        __syncthreads();
        if (cig + 1 < CCH/4) {
            r0 = load_mid(mn, cig + 1, tid, h0, w0);
            r1 = (tid + 256 < 324) ? load_mid(mn, cig + 1, tid + 256, h0, w0) : 0u;
        }
        const int* wp = &ws2[cig*9*CCH + cog*8];
        #pragma unroll
        for (int k = 0; k < 9; k++) {
            int kh = k / 3, kw = k % 3;
            int4 wa = *(const int4*)(wp + k*CCH);
            int4 wb = *(const int4*)(wp + k*CCH + 4);
            #pragma unroll
            for (int p = 0; p < 4; p++) {
                int pix = p0 + 64*p;
                int hh = pix >> 4, wc = pix & 15;
                int xv = (int)patch[buf][(hh + kh)*18 + wc + kw];
                acc[p][0] = __dp4a(xv, wa.x, acc[p][0]);
                acc[p][1] = __dp4a(xv, wa.y, acc[p][1]);
                acc[p][2] = __dp4a(xv, wa.z, acc[p][2]);
                acc[p][3] = __dp4a(xv, wa.w, acc[p][3]);
                acc[p][4] = __dp4a(xv, wb.x, acc[p][4]);
                acc[p][5] = __dp4a(xv, wb.y, acc[p][5]);
                acc[p][6] = __dp4a(xv, wb.z, acc[p][6]);
                acc[p][7] = __dp4a(xv, wb.w, acc[p][7]);
            }
        }
        __syncthreads();
    }

    int IT0[8], ID[8];
    #pragma unroll
    for (int j = 0; j < 8; j++) {
        IT0[j] = g_lut2_t0[cog*8 + j];
        ID[j]  = g_lut2_d[cog*8 + j];
    }
    #pragma unroll
    for (int p = 0; p < 4; p++) {
        int pix = p0 + 64*p;
        int hh = pix >> 4, wc = pix & 15;
        int gh = h0 + hh, gw = w0 + wc;
        #pragma unroll
        for (int j = 0; j < 8; j++) {
            int s = acc[p][j];
            int lvl = 0;
            #pragma unroll
            for (int jj = 0; jj < 7; jj++) {
                int th = IT0[j] + jj * ID[j];
                lvl += (jj & 1) ? (s >= th) : (s > th);
            }
            int co = cog*8 + j;
            out[(((size_t)n*CCH + co)*HH + gh)*WW + gw] = (float)lvl;
        }
    }
}

// ---------------------------------------------------------------------------
extern "C" void kernel_launch(void* const* d_in, const int* in_sizes, int n_in,
                              void* d_out, int out_size) {
    const float* x       = (const float*)d_in[0];
    const float* conv1_w = (const float*)d_in[1];
    const float* conv2_w = (const float*)d_in[2];
    const float* bn1_w   = (const float*)d_in[3];
    const float* bn1_b   = (const float*)d_in[4];
    const float* bn1_m   = (const float*)d_in[5];
    const float* bn1_v   = (const float*)d_in[6];
    const float* bn2_w   = (const float*)d_in[7];
    const float* bn2_b   = (const float*)d_in[8];
    const float* bn2_m   = (const float*)d_in[9];
    const float* bn2_v   = (const float*)d_in[10];
    const float* a1      = (const float*)d_in[11];
    const float* a2      = (const float*)d_in[12];
    const float* ns      = (const float*)d_in[13];

    setup_kernel<<<CCH, KELEMS>>>(conv1_w, conv2_w,
                                  bn1_w, bn1_b, bn1_m, bn1_v,
                                  bn2_w, bn2_b, bn2_m, bn2_v,
                                  a1, a2, ns);

    dim3 pgrid(HH, BB);
    prepass_kernel<<<pgrid, 256>>>(x);

    cudaFuncSetAttribute(conv1_imma_kernel,
                         cudaFuncAttributeMaxDynamicSharedMemorySize, SMEM1_TOT);
    dim3 grid1(WW/16, HH/8, BB);
    conv1_imma_kernel<<<grid1, 256, SMEM1_TOT>>>();

    dim3 grid2(WW/16, HH/16, BB);
    conv2_kernel<<<grid2, 256>>>((float*)d_out);
}

// round 9
// speedup vs baseline: 1.8757x; 1.1680x over previous
#include <cuda_runtime.h>
#include <cstdint>

#define CCH 32
#define HH 224
#define WW 224
#define BB 16
#define KELEMS (CCH*9)   // 288 weight elems per out channel

// ---------------- device scratch ----------------
// conv1 weights int8, single plane: [pos 9][co 32][ci 32]
__device__ signed char g_w1b[9*CCH*CCH];
// conv2 weights packed int8x4 over ci groups: [cig][k][co]
__device__ int   g_w2[(CCH/4)*9*CCH];
// LUT params
__device__ float g_lut1_t0[CCH], g_lut1_d[CCH];
__device__ int   g_lut2_t0[CCH], g_lut2_d[CCH];
// quantized input: per pixel 96 bytes = 24 words [plane*32+ci], q = rint(x*2^20)
__device__ unsigned int g_xt[(size_t)BB*HH*WW*24];
// intermediate levels, 4 channels packed per uint32: [n][cig][h][w]
__device__ unsigned int g_mid[(size_t)BB*(CCH/4)*HH*WW];

// ---------------- PTX helpers ----------------
#define LDSM4(r0,r1,r2,r3,addr)                                              \
    asm volatile("ldmatrix.sync.aligned.m8n8.x4.shared.b16 {%0,%1,%2,%3}, [%4];" \
        : "=r"(r0), "=r"(r1), "=r"(r2), "=r"(r3) : "r"(addr))

#define MMA_S8(c0,c1,c2,c3,a0,a1,a2,a3,b0,b1)                                \
    asm("mma.sync.aligned.m16n8k32.row.col.s32.s8.s8.s32 "                   \
        "{%0,%1,%2,%3}, {%4,%5,%6,%7}, {%8,%9}, {%0,%1,%2,%3};"              \
        : "+r"(c0), "+r"(c1), "+r"(c2), "+r"(c3)                             \
        : "r"(a0), "r"(a1), "r"(a2), "r"(a3), "r"(b0), "r"(b1))

// ---------------------------------------------------------------------------
// Setup
// ---------------------------------------------------------------------------
__global__ void setup_kernel(const float* __restrict__ conv1_w,
                             const float* __restrict__ conv2_w,
                             const float* __restrict__ bn1_w, const float* __restrict__ bn1_b,
                             const float* __restrict__ bn1_m, const float* __restrict__ bn1_v,
                             const float* __restrict__ bn2_w, const float* __restrict__ bn2_b,
                             const float* __restrict__ bn2_m, const float* __restrict__ bn2_v,
                             const float* __restrict__ a1p, const float* __restrict__ a2p,
                             const float* __restrict__ nsp) {
    __shared__ float red[KELEMS];
    __shared__ float mean1s, mean2s;
    __shared__ int   ssm[KELEMS];
    int co = blockIdx.x;
    int t  = threadIdx.x;           // 288 threads

    float v1 = conv1_w[co*KELEMS + t];
    float v2 = conv2_w[co*KELEMS + t];

    red[t] = v1; __syncthreads();
    if (t < 32) red[t] += red[t + 256];
    __syncthreads();
    for (int s = 128; s > 0; s >>= 1) { if (t < s) red[t] += red[t + s]; __syncthreads(); }
    if (t == 0) mean1s = red[0] * (1.f / 288.f);
    __syncthreads();
    float m1 = mean1s;
    __syncthreads();

    red[t] = v2; __syncthreads();
    if (t < 32) red[t] += red[t + 256];
    __syncthreads();
    for (int s = 128; s > 0; s >>= 1) { if (t < s) red[t] += red[t + s]; __syncthreads(); }
    if (t == 0) mean2s = red[0] * (1.f / 288.f);
    __syncthreads();
    float m2 = mean2s;

    int ci = t / 9, k = t % 9;
    {
        float d1 = v1 - m1;
        g_w1b[(k*CCH + co)*CCH + ci] = (d1 > 0.f) ? 1 : ((d1 < 0.f) ? -1 : 0);
    }

    float s2f = v2 - m2;
    ssm[t] = (s2f > 0.f) ? 1 : ((s2f < 0.f) ? -1 : 0);
    __syncthreads();
    if (t < (CCH/4)*9) {
        int cig = t / 9, kk = t % 9;
        int pk = 0;
        #pragma unroll
        for (int b = 0; b < 4; b++) {
            int s = ssm[(cig*4 + b)*9 + kk];
            pk |= (s & 0xFF) << (8*b);
        }
        g_w2[(cig*9 + kk)*CCH + co] = pk;
    }

    if (t == 0) {
        float a1 = *a1p, a2 = *a2p, ns = *nsp;
        {
            float std = sqrtf(bn1_v[co] + 1e-5f);
            float w = bn1_w[co] / std;
            float b = bn1_b[co] - w * bn1_m[co];
            float den = a1 * w;
            float t0 = rintf((0.5f * a2 - b) / den);
            float t1 = rintf((1.5f * a2 - b) / den);
            g_lut1_t0[co] = t0;
            g_lut1_d[co]  = t1 - t0;
        }
        {
            float std = sqrtf(bn2_v[co] + 1e-5f);
            float w = bn2_w[co] / std;
            float b = bn2_b[co] - w * bn2_m[co];
            float den = a2 * w;
            float t0 = rintf((0.5f * ns - b) / den);
            float t1 = rintf((1.5f * ns - b) / den);
            g_lut2_t0[co] = (int)t0;
            g_lut2_d[co]  = (int)(t1 - t0);
        }
    }
}

// ---------------------------------------------------------------------------
// Pre-pass: NCHW fp32 -> per-pixel 96 int8 [plane*32+ci], q = rint(x*2^20)
// signed-digit: q = b0 + 256 b1 + 65536 b2  (b0,b1 in [-128,127], |b2|<=~90)
// ---------------------------------------------------------------------------
__global__ void __launch_bounds__(256)
prepass_kernel(const float* __restrict__ x) {
    __shared__ signed char stage[WW*100];   // [w][100B slot: 96 data + 4 pad]
    int n = blockIdx.y, h = blockIdx.x;
    int tid = threadIdx.x;

    for (int idx = tid; idx < CCH*WW; idx += 256) {
        int ci = idx / WW, w = idx % WW;        // lanes: w consecutive -> coalesced
        float v = x[(((size_t)n*CCH + ci)*HH + h)*WW + w];
        int q = __float2int_rn(v * 1048576.f);
        int b0 = (int)(signed char)(q & 0xFF);
        int q1 = (q - b0) >> 8;
        int b1 = (int)(signed char)(q1 & 0xFF);
        int b2 = (q1 - b1) >> 8;                 // |b2| <= ~90
        stage[w*100 +  0 + ci] = (signed char)b0;
        stage[w*100 + 32 + ci] = (signed char)b1;
        stage[w*100 + 64 + ci] = (signed char)b2;
    }
    __syncthreads();
    const unsigned* sw = (const unsigned*)stage;
    unsigned* dst = g_xt + ((size_t)n*HH + h)*WW*24;
    for (int idx = tid; idx < WW*24; idx += 256) {
        int w = idx / 24, c = idx % 24;
        dst[idx] = sw[w*25 + c];                // coalesced dst, conflict-free src
    }
}

// ---------------------------------------------------------------------------
// Conv1 via raw IMMA m16n8k32, 3 planes, B-frags shared across planes.
// CTA: 256 threads / 8 warps. Output tile: 8h x 16w x 32co. Warp owns row oh=wid.
// Patch P[10][18] slots x 112B stride (96B data); Weights Wt[9*32] x 48B stride.
// ---------------------------------------------------------------------------
#define PSTR8 112
#define WSTR8 48
#define P_BYTES (180*PSTR8)           // 20160
#define W_BYTES (288*WSTR8)           // 13824
#define SMEM1_TOT (P_BYTES + W_BYTES) // 33984

__global__ void __launch_bounds__(256)
conv1_imma_kernel() {
    extern __shared__ __align__(16) char smem[];
    signed char* P  = (signed char*)smem;            // [180][112]
    signed char* Wt = (signed char*)(smem + P_BYTES);// [288][48]
    unsigned* P32 = (unsigned*)P;
    unsigned* W32 = (unsigned*)Wt;

    int tid = threadIdx.x;
    int wid = tid >> 5, lid = tid & 31;

    int n  = blockIdx.z;
    int h0 = blockIdx.y * 8;
    int w0 = blockIdx.x * 16;

    // weights: 288 rows x 8 words (smem stride 12 words)
    for (int idx = tid; idx < 288*8; idx += 256) {
        int row = idx >> 3, c = idx & 7;
        W32[row*12 + c] = ((const unsigned*)g_w1b)[idx];
    }
    // patch: 180 slots x 24 words (smem stride 28 words)
    for (int idx = tid; idx < 180*24; idx += 256) {
        int slot = idx / 24, c = idx % 24;
        int ph = slot / 18, pw = slot % 18;
        int gh = h0 - 1 + ph, gw = w0 - 1 + pw;
        bool ok = (gh >= 0 && gh < HH && gw >= 0 && gw < WW);
        const unsigned* src = g_xt + (((size_t)n*HH + (ok ? gh : 0))*WW + (ok ? gw : 0))*24;
        P32[slot*28 + c] = ok ? src[c] : 0u;
    }
    __syncthreads();

    unsigned Pb = (unsigned)__cvta_generic_to_shared(P);
    unsigned Wb = (unsigned)__cvta_generic_to_shared(Wt);

    // accumulators: [plane 3][ntile 4][reg 4]
    int c[3][4][4];
    #pragma unroll
    for (int p = 0; p < 3; p++)
        #pragma unroll
        for (int t = 0; t < 4; t++)
            #pragma unroll
            for (int i = 0; i < 4; i++) c[p][t][i] = 0;

    int oh = wid;
    int apix  = (lid < 16) ? lid : (lid - 16);
    int akadd = (lid < 16) ? 0 : 16;
    int bco   = ((lid >> 4) << 3) + (lid & 7);
    int bkadd = ((lid >> 3) & 1) * 16;

    #pragma unroll 3
    for (int pos = 0; pos < 9; pos++) {
        int kh = pos / 3, kw = pos % 3;
        unsigned aaddr = Pb + (unsigned)(((oh + kh)*18 + kw + apix)*PSTR8 + akadd);
        unsigned baddr = Wb + (unsigned)((pos*32 + bco)*WSTR8 + bkadd);
        // B frags once per pos (shared by all planes)
        unsigned b0, b1, b2, b3, b4, b5, b6, b7;
        LDSM4(b0, b1, b2, b3, baddr);                 // co 0-15
        LDSM4(b4, b5, b6, b7, baddr + 16*WSTR8);      // co 16-31
        #pragma unroll
        for (int p = 0; p < 3; p++) {
            unsigned a0, a1, a2, a3;
            LDSM4(a0, a1, a2, a3, aaddr + p*32);
            MMA_S8(c[p][0][0], c[p][0][1], c[p][0][2], c[p][0][3], a0, a1, a2, a3, b0, b1);
            MMA_S8(c[p][1][0], c[p][1][1], c[p][1][2], c[p][1][3], a0, a1, a2, a3, b2, b3);
            MMA_S8(c[p][2][0], c[p][2][1], c[p][2][2], c[p][2][3], a0, a1, a2, a3, b4, b5);
            MMA_S8(c[p][3][0], c[p][3][1], c[p][3][2], c[p][3][3], a0, a1, a2, a3, b6, b7);
        }
    }

    // epilogue: exact int64 sums -> integer LUT (thresholds << 20) -> pack via shfl
    int gh  = h0 + oh;
    int row = lid >> 2;
    int colq = lid & 3;
    #pragma unroll
    for (int t = 0; t < 4; t++) {
        int co0 = 8*t + 2*colq;
        long long T0a = (long long)g_lut1_t0[co0],   Da = (long long)g_lut1_d[co0];
        long long T0b = (long long)g_lut1_t0[co0+1], Db = (long long)g_lut1_d[co0+1];
        unsigned half[2];
        #pragma unroll
        for (int rpair = 0; rpair < 2; rpair++) {   // 0: row, 1: row+8
            int i0 = rpair*2, i1 = rpair*2 + 1;
            long long S0 = (long long)(c[0][t][i0] + (c[1][t][i0] << 8))
                         + ((long long)c[2][t][i0] << 16);
            long long S1 = (long long)(c[0][t][i1] + (c[1][t][i1] << 8))
                         + ((long long)c[2][t][i1] << 16);
            int l0 = 0, l1 = 0;
            #pragma unroll
            for (int jj = 0; jj < 7; jj++) {
                long long tha = (T0a + (long long)jj * Da) << 20;
                long long thb = (T0b + (long long)jj * Db) << 20;
                l0 += (jj & 1) ? (S0 >= tha) : (S0 > tha);
                l1 += (jj & 1) ? (S1 >= thb) : (S1 > thb);
            }
            half[rpair] = (unsigned)l0 | ((unsigned)l1 << 8);
        }
        unsigned pA = __shfl_xor_sync(0xFFFFFFFFu, half[0], 1);
        unsigned pB = __shfl_xor_sync(0xFFFFFFFFu, half[1], 1);
        if (!(lid & 1)) {
            int cig = 2*t + (colq >> 1);
            size_t base = (((size_t)n*(CCH/4) + cig)*HH + gh)*WW + w0;
            g_mid[base + row]     = half[0] | (pA << 16);
            g_mid[base + row + 8] = half[1] | (pB << 16);
        }
    }
}

// ---------------------------------------------------------------------------
// Conv2 (exact int8 via dp4a) fused with LUT2 -> fp32 output.
// 512 threads / 16 warps, 2 px x 8 co per thread, 2 CTAs/SM (50% occ).
// ---------------------------------------------------------------------------
__device__ __forceinline__ unsigned load_mid(const unsigned* __restrict__ mn, int cig,
                                             int idx, int h0, int w0) {
    int ph = idx / 18, pw = idx % 18;
    int gh = h0 - 1 + ph, gw = w0 - 1 + pw;
    if (gh < 0 || gh >= HH || gw < 0 || gw >= WW) return 0u;
    return mn[(size_t)cig*HH*WW + gh*WW + gw];
}

__global__ void __launch_bounds__(512, 2)
conv2_kernel(float* __restrict__ out) {
    __shared__ int ws2[(CCH/4)*9*CCH];     // 9216 B
    __shared__ unsigned patch[2][18*18];

    int n  = blockIdx.z;
    int h0 = blockIdx.y * 16, w0 = blockIdx.x * 16;
    int tid = threadIdx.x;

    for (int i = tid; i < (CCH/4)*9*CCH; i += 512) ws2[i] = g_w2[i];

    int cog = tid >> 7;          // 0..3 -> 8 out channels
    int p0  = tid & 127;         // pixels p0 and p0+128

    int acc[2][8];
    #pragma unroll
    for (int p = 0; p < 2; p++)
        #pragma unroll
        for (int j = 0; j < 8; j++) acc[p][j] = 0;

    const unsigned* mn = g_mid + (size_t)n*(CCH/4)*HH*WW;

    unsigned r0 = (tid < 324) ? load_mid(mn, 0, tid, h0, w0) : 0u;

    for (int cig = 0; cig < CCH/4; cig++) {
        int buf = cig & 1;
        if (tid < 324) patch[buf][tid] = r0;
        __syncthreads();
        if (cig + 1 < CCH/4 && tid < 324)
            r0 = load_mid(mn, cig + 1, tid, h0, w0);
        const int* wp = &ws2[cig*9*CCH + cog*8];
        #pragma unroll
        for (int k = 0; k < 9; k++) {
            int kh = k / 3, kw = k % 3;
            int4 wa = *(const int4*)(wp + k*CCH);
            int4 wb = *(const int4*)(wp + k*CCH + 4);
            #pragma unroll
            for (int p = 0; p < 2; p++) {
                int pix = p0 + 128*p;
                int hh = pix >> 4, wc = pix & 15;
                int xv = (int)patch[buf][(hh + kh)*18 + wc + kw];
                acc[p][0] = __dp4a(xv, wa.x, acc[p][0]);
                acc[p][1] = __dp4a(xv, wa.y, acc[p][1]);
                acc[p][2] = __dp4a(xv, wa.z, acc[p][2]);
                acc[p][3] = __dp4a(xv, wa.w, acc[p][3]);
                acc[p][4] = __dp4a(xv, wb.x, acc[p][4]);
                acc[p][5] = __dp4a(xv, wb.y, acc[p][5]);
                acc[p][6] = __dp4a(xv, wb.z, acc[p][6]);
                acc[p][7] = __dp4a(xv, wb.w, acc[p][7]);
            }
        }
        __syncthreads();
    }

    int IT0[8], ID[8];
    #pragma unroll
    for (int j = 0; j < 8; j++) {
        IT0[j] = g_lut2_t0[cog*8 + j];
        ID[j]  = g_lut2_d[cog*8 + j];
    }
    #pragma unroll
    for (int p = 0; p < 2; p++) {
        int pix = p0 + 128*p;
        int hh = pix >> 4, wc = pix & 15;
        int gh = h0 + hh, gw = w0 + wc;
        #pragma unroll
        for (int j = 0; j < 8; j++) {
            int s = acc[p][j];
            int lvl = 0;
            #pragma unroll
            for (int jj = 0; jj < 7; jj++) {
                int th = IT0[j] + jj * ID[j];
                lvl += (jj & 1) ? (s >= th) : (s > th);
            }
            int co = cog*8 + j;
            out[(((size_t)n*CCH + co)*HH + gh)*WW + gw] = (float)lvl;
        }
    }
}

// ---------------------------------------------------------------------------
extern "C" void kernel_launch(void* const* d_in, const int* in_sizes, int n_in,
                              void* d_out, int out_size) {
    const float* x       = (const float*)d_in[0];
    const float* conv1_w = (const float*)d_in[1];
    const float* conv2_w = (const float*)d_in[2];
    const float* bn1_w   = (const float*)d_in[3];
    const float* bn1_b   = (const float*)d_in[4];
    const float* bn1_m   = (const float*)d_in[5];
    const float* bn1_v   = (const float*)d_in[6];
    const float* bn2_w   = (const float*)d_in[7];
    const float* bn2_b   = (const float*)d_in[8];
    const float* bn2_m   = (const float*)d_in[9];
    const float* bn2_v   = (const float*)d_in[10];
    const float* a1      = (const float*)d_in[11];
    const float* a2      = (const float*)d_in[12];
    const float* ns      = (const float*)d_in[13];

    setup_kernel<<<CCH, KELEMS>>>(conv1_w, conv2_w,
                                  bn1_w, bn1_b, bn1_m, bn1_v,
                                  bn2_w, bn2_b, bn2_m, bn2_v,
                                  a1, a2, ns);

    dim3 pgrid(HH, BB);
    prepass_kernel<<<pgrid, 256>>>(x);

    cudaFuncSetAttribute(conv1_imma_kernel,
                         cudaFuncAttributeMaxDynamicSharedMemorySize, SMEM1_TOT);
    dim3 grid1(WW/16, HH/8, BB);
    conv1_imma_kernel<<<grid1, 256, SMEM1_TOT>>>();

    dim3 grid2(WW/16, HH/16, BB);
    conv2_kernel<<<grid2, 512>>>((float*)d_out);
}